// round 1
// baseline (speedup 1.0000x reference)
#include <cuda_runtime.h>

// Inverse 2D Haar DWT, collapsed to the per-2x2-block butterfly:
//   out[2i  ,2j  ] = 0.5*(LL + LH + HL + HH)
//   out[2i  ,2j+1] = 0.5*(LL - LH + HL - HH)
//   out[2i+1,2j  ] = 0.5*(LL + LH - HL - HH)
//   out[2i+1,2j+1] = 0.5*(LL - LH - HL + HH)
// (reflect-pad row/col in the reference lands on zeros, so it vanishes)
//
// Shapes: in  (32,128,56,56) f32 x4  -> out (32,128,112,112) f32
// Each thread: float2 load from each subband (2 input cols), 2x float4 stores.

#define H_IN   56
#define W_IN   56
#define H_OUT  112
#define W_OUT  112
#define WPAIRS (W_IN / 2)   // 28

__global__ __launch_bounds__(256)
void idwt_haar_kernel(const float* __restrict__ LL,
                      const float* __restrict__ LH,
                      const float* __restrict__ HL,
                      const float* __restrict__ HH,
                      float* __restrict__ out,
                      int total)   // = N*C*H_IN*WPAIRS
{
    int idx = blockIdx.x * blockDim.x + threadIdx.x;
    if (idx >= total) return;

    int jj = idx % WPAIRS;                 // input col pair -> cols 2jj, 2jj+1
    int t  = idx / WPAIRS;
    int i  = t % H_IN;                     // input row
    int ch = t / H_IN;                     // fused (batch*channel)

    long in_off  = (long)ch * (H_IN * W_IN) + i * W_IN + 2 * jj;
    long out_off = (long)ch * (H_OUT * W_OUT) + (2 * i) * W_OUT + 4 * jj;

    float2 ll = *reinterpret_cast<const float2*>(LL + in_off);
    float2 lh = *reinterpret_cast<const float2*>(LH + in_off);
    float2 hl = *reinterpret_cast<const float2*>(HL + in_off);
    float2 hh = *reinterpret_cast<const float2*>(HH + in_off);

    // butterfly, element 0
    float p0 = ll.x + hl.x, m0 = ll.x - hl.x;
    float q0 = lh.x + hh.x, r0 = lh.x - hh.x;
    // butterfly, element 1
    float p1 = ll.y + hl.y, m1 = ll.y - hl.y;
    float q1 = lh.y + hh.y, r1 = lh.y - hh.y;

    float4 row_even = make_float4(0.5f * (p0 + q0), 0.5f * (p0 - q0),
                                  0.5f * (p1 + q1), 0.5f * (p1 - q1));
    float4 row_odd  = make_float4(0.5f * (m0 + r0), 0.5f * (m0 - r0),
                                  0.5f * (m1 + r1), 0.5f * (m1 - r1));

    *reinterpret_cast<float4*>(out + out_off)         = row_even;
    *reinterpret_cast<float4*>(out + out_off + W_OUT) = row_odd;
}

extern "C" void kernel_launch(void* const* d_in, const int* in_sizes, int n_in,
                              void* d_out, int out_size)
{
    const float* LL = (const float*)d_in[0];
    const float* LH = (const float*)d_in[1];
    const float* HL = (const float*)d_in[2];
    const float* HH = (const float*)d_in[3];
    float* out = (float*)d_out;

    // total thread count: N*C*H*W/2 elements-pairs
    int total = in_sizes[0] / 2;   // 32*128*56*56 / 2 = 6,422,528
    int threads = 256;
    int blocks = (total + threads - 1) / threads;

    idwt_haar_kernel<<<blocks, threads>>>(LL, LH, HL, HH, out, total);
}